// round 2
// baseline (speedup 1.0000x reference)
#include <cuda_runtime.h>
#include <cstdint>
#include <cstddef>

// Problem constants
#define BB   32
#define NN   128
#define IND  32
#define OUTD 64

// Scratch: [b][e][p][q] layouts, fp32. 3 x 128 MiB device globals.
__device__ float g_s1[(size_t)BB * OUTD * NN * NN];   // X1 transposed: [b,e,i,k]
__device__ float g_s2[(size_t)BB * OUTD * NN * NN];   // X2 transposed: [b,e,k,j]
__device__ float g_to[(size_t)BB * OUTD * NN * NN];   // out transposed: [b,e,i,j]

// ---------------------------------------------------------------------------
// Stage 1: per-tuple MLP (Linear+ReLU for W1 and W2), masked, written
// transposed to [b,e,p,q] so stage 2 sees contiguous 128x128 matrices.
// Grid: B*N blocks (b = blk>>7, p = blk&127). Block: 128 threads (q).
// ---------------------------------------------------------------------------
__global__ void __launch_bounds__(128) stage1_kernel(
    const float* __restrict__ X,
    const float* __restrict__ W1, const float* __restrict__ b1,
    const float* __restrict__ W2, const float* __restrict__ b2,
    const int*   __restrict__ nn32)   // n_nodes viewed as int32 words
{
    __shared__ float w1[OUTD * IND];   // [e][d] (transposed for contiguous d)
    __shared__ float w2[OUTD * IND];
    __shared__ float bb1[OUTD], bb2[OUTD];

    const int b = blockIdx.x >> 7;
    const int p = blockIdx.x & 127;
    const int q = threadIdx.x;

    // Load weights transposed into smem
    for (int l = q; l < IND * OUTD; l += 128) {
        int d = l >> 6;        // W layout: [d][e], e fastest
        int e = l & 63;
        w1[e * IND + d] = W1[l];
        w2[e * IND + d] = W2[l];
    }
    if (q < OUTD) { bb1[q] = b1[q]; bb2[q] = b2[q]; }
    __syncthreads();

    // n_nodes dtype defense: if int64, odd int32 words are 0 (all n>=1).
    int n;
    if (nn32[1] == 0) n = nn32[2 * b];   // int64 little-endian low word
    else              n = nn32[b];       // int32

    const bool act = (p < n) && (q < n);

    // Load this tuple's 32 features (always in-bounds; mask only at store)
    float4 x4[8];
    const float4* Xp = reinterpret_cast<const float4*>(
        X + (((size_t)b * NN + p) * NN + q) * IND);
#pragma unroll
    for (int i = 0; i < 8; i++) x4[i] = Xp[i];

    const size_t base = (((size_t)b * OUTD) * NN + p) * NN + q;  // + e*NN*NN

#pragma unroll 2
    for (int e = 0; e < OUTD; e++) {
        const float4* w1e = reinterpret_cast<const float4*>(w1 + e * IND);
        const float4* w2e = reinterpret_cast<const float4*>(w2 + e * IND);
        float v1 = bb1[e];
        float v2 = bb2[e];
#pragma unroll
        for (int i = 0; i < 8; i++) {
            float4 xv = x4[i];
            float4 a = w1e[i];
            float4 c = w2e[i];
            v1 += xv.x * a.x + xv.y * a.y + xv.z * a.z + xv.w * a.w;
            v2 += xv.x * c.x + xv.y * c.y + xv.z * c.z + xv.w * c.w;
        }
        v1 = act ? fmaxf(v1, 0.0f) : 0.0f;
        v2 = act ? fmaxf(v2, 0.0f) : 0.0f;
        g_s1[base + (size_t)e * (NN * NN)] = v1;
        g_s2[base + (size_t)e * (NN * NN)] = v2;
    }
}

// ---------------------------------------------------------------------------
// Stage 2: 2048 independent 128x128x128 fp32 GEMMs (one CTA per (b,e)).
// A transposed in smem, B straight. Both padded to 132 floats/row so every
// row base is 16B-aligned (float4 LDS.128 legal). 256 threads, each an 8x8
// register tile split 4+4 for conflict-free smem access.
// ---------------------------------------------------------------------------
#define APAD 132
#define BPAD 132

__global__ void __launch_bounds__(256, 1) stage2_kernel()
{
    const int be = blockIdx.x;                       // b*64 + e
    const float* __restrict__ A  = g_s1 + (size_t)be * (NN * NN);
    const float* __restrict__ Bm = g_s2 + (size_t)be * (NN * NN);
    float* __restrict__       C  = g_to + (size_t)be * (NN * NN);

    extern __shared__ float sm[];
    float* At = sm;                 // [128][APAD]  At[k][i] = A[i][k]
    float* Bs = sm + NN * APAD;     // [128][BPAD]  Bs[k][j]

    const int tid = threadIdx.x;

    // Load A transposed (coalesced gmem reads; smem stores have a 4-way
    // conflict from the stride-132 pattern — one-time cost, negligible).
    for (int l = tid; l < NN * NN; l += 256) {
        int i = l >> 7;
        int k = l & 127;
        At[k * APAD + i] = A[l];
    }
    // Load B straight with float4
    const float4* B4 = reinterpret_cast<const float4*>(Bm);
    for (int l = tid; l < (NN * NN) / 4; l += 256) {
        int k  = l >> 5;
        int j4 = l & 31;
        *reinterpret_cast<float4*>(&Bs[k * BPAD + j4 * 4]) = B4[l];
    }
    __syncthreads();

    const int tx = tid & 15;   // column group
    const int ty = tid >> 4;   // row group
    // rows: {4ty..4ty+3, 64+4ty..64+4ty+3}; cols: {4tx.., 64+4tx..}

    float acc[8][8];
#pragma unroll
    for (int i = 0; i < 8; i++)
#pragma unroll
        for (int j = 0; j < 8; j++) acc[i][j] = 0.0f;

    for (int k = 0; k < NN; k++) {
        float4 a0 = *reinterpret_cast<const float4*>(&At[k * APAD + 4 * ty]);
        float4 a1 = *reinterpret_cast<const float4*>(&At[k * APAD + 64 + 4 * ty]);
        float4 b0 = *reinterpret_cast<const float4*>(&Bs[k * BPAD + 4 * tx]);
        float4 b1 = *reinterpret_cast<const float4*>(&Bs[k * BPAD + 64 + 4 * tx]);
        float a[8] = {a0.x, a0.y, a0.z, a0.w, a1.x, a1.y, a1.z, a1.w};
        float bv[8] = {b0.x, b0.y, b0.z, b0.w, b1.x, b1.y, b1.z, b1.w};
#pragma unroll
        for (int i = 0; i < 8; i++)
#pragma unroll
            for (int j = 0; j < 8; j++)
                acc[i][j] += a[i] * bv[j];
    }

#pragma unroll
    for (int ri = 0; ri < 8; ri++) {
        int i = (ri < 4) ? (4 * ty + ri) : (64 + 4 * ty + (ri - 4));
        *reinterpret_cast<float4*>(&C[i * NN + 4 * tx]) =
            make_float4(acc[ri][0], acc[ri][1], acc[ri][2], acc[ri][3]);
        *reinterpret_cast<float4*>(&C[i * NN + 64 + 4 * tx]) =
            make_float4(acc[ri][4], acc[ri][5], acc[ri][6], acc[ri][7]);
    }
}

// ---------------------------------------------------------------------------
// Final transpose: out[b, x, e] = g_to[b, e, x]   (x = i*128+j, 16384 values)
// Classic 32x32 smem-tiled transpose per b.
// Grid: (16384/32, 64/32, 32). Block: (32, 8).
// ---------------------------------------------------------------------------
__global__ void __launch_bounds__(256) transpose_kernel(float* __restrict__ out)
{
    __shared__ float t[32][33];
    const int b  = blockIdx.z;
    const int x0 = blockIdx.x * 32;
    const int e0 = blockIdx.y * 32;
    const int tx = threadIdx.x;
    const int ty = threadIdx.y;

    const float* src = g_to + (size_t)b * OUTD * (NN * NN);

#pragma unroll
    for (int j = 0; j < 32; j += 8)
        t[ty + j][tx] = src[(size_t)(e0 + ty + j) * (NN * NN) + x0 + tx];
    __syncthreads();
#pragma unroll
    for (int j = 0; j < 32; j += 8)
        out[((size_t)b * (NN * NN) + x0 + ty + j) * OUTD + e0 + tx] = t[tx][ty + j];
}

// ---------------------------------------------------------------------------
extern "C" void kernel_launch(void* const* d_in, const int* in_sizes, int n_in,
                              void* d_out, int out_size)
{
    const float* X  = (const float*)d_in[0];
    const float* W1 = (const float*)d_in[1];
    const float* b1 = (const float*)d_in[2];
    const float* W2 = (const float*)d_in[3];
    const float* b2 = (const float*)d_in[4];
    const int*   nn = (const int*)d_in[5];   // int32 or int64 words; detected in-kernel
    float* out = (float*)d_out;

    // Stage 1
    stage1_kernel<<<BB * NN, 128>>>(X, W1, b1, W2, b2, nn);

    // Stage 2: ~132KB dynamic smem
    const int smem = (NN * APAD + NN * BPAD) * (int)sizeof(float);  // 135,168 B
    cudaFuncSetAttribute(stage2_kernel,
                         cudaFuncAttributeMaxDynamicSharedMemorySize, smem);
    stage2_kernel<<<BB * OUTD, 256, smem>>>();

    // Transpose to [b,i,j,e]
    dim3 tg(NN * NN / 32, OUTD / 32, BB);
    transpose_kernel<<<tg, dim3(32, 8)>>>(out);
}

// round 5
// speedup vs baseline: 2.3153x; 2.3153x over previous
#include <cuda_runtime.h>
#include <cuda_bf16.h>
#include <cstdint>
#include <cstddef>

// Problem constants
#define BB   32
#define NN   128
#define IND  32
#define OUTD 64

// Scratch (device globals; no allocs allowed)
__device__ __nv_bfloat16 g_s1[(size_t)BB * OUTD * NN * NN];  // X1: [b,e,i,k]
__device__ __nv_bfloat16 g_s2[(size_t)BB * OUTD * NN * NN];  // X2^T: [b,e,j,k]
__device__ float         g_to[(size_t)BB * OUTD * NN * NN];  // out: [b,e,i,j]

__device__ __forceinline__ uint32_t smem_u32(const void* p) {
    uint32_t a;
    asm("{ .reg .u64 t; cvta.to.shared.u64 t, %1; cvt.u32.u64 %0, t; }"
        : "=r"(a) : "l"(p));
    return a;
}

// ---------------------------------------------------------------------------
// MLP pass: fp32 register-tiled GEMM  [128 t x 32 k] @ [32 k x 64 e]
// pass2=0: block=(b,p) computes X1[b,p,t,e]  -> dst[b,e,p,t]   (K-major A)
// pass2=1: block=(b,q) computes X2[b,t,q,e]  -> dst[b,e,q,t]   (K-major B^T)
// Thread (tx,ty): t = 4*tx..4*tx+3 (consecutive), e = 16*ty..16*ty+15.
// ---------------------------------------------------------------------------
__global__ void __launch_bounds__(128) mlp_kernel(
    const float* __restrict__ X, const float* __restrict__ W,
    const float* __restrict__ bias, const int* __restrict__ nn32,
    __nv_bfloat16* __restrict__ dst, const int pass2)
{
    __shared__ float Xs[IND][NN];    // [k][t]
    __shared__ float Ws[IND][OUTD];  // [k][e]
    __shared__ float bs[OUTD];

    const int b   = blockIdx.x >> 7;
    const int row = blockIdx.x & 127;
    const int tid = threadIdx.x;

    for (int l = tid; l < IND * OUTD; l += 128) Ws[l >> 6][l & 63] = W[l];
    if (tid < OUTD) bs[tid] = bias[tid];

    {   // load this block's 128 X rows, transposed into Xs[k][t]
        const int t = tid;
        const size_t xoff = pass2 ? (((size_t)b * NN + t) * NN + row) * IND
                                  : (((size_t)b * NN + row) * NN + t) * IND;
        const float4* Xp = reinterpret_cast<const float4*>(X + xoff);
#pragma unroll
        for (int c = 0; c < 8; c++) {
            float4 v = Xp[c];
            Xs[4 * c + 0][t] = v.x; Xs[4 * c + 1][t] = v.y;
            Xs[4 * c + 2][t] = v.z; Xs[4 * c + 3][t] = v.w;
        }
    }
    __syncthreads();

    const int n = (nn32[1] == 0) ? nn32[2 * b] : nn32[b];   // int64 vs int32 defense

    const int tx = tid & 31;   // t = 4*tx + i
    const int ty = tid >> 5;   // e = 16*ty + j

    float acc[4][16];
#pragma unroll
    for (int i = 0; i < 4; i++)
#pragma unroll
        for (int j = 0; j < 16; j++) acc[i][j] = bs[16 * ty + j];

#pragma unroll 4
    for (int k = 0; k < IND; k++) {
        float4 av = *reinterpret_cast<const float4*>(&Xs[k][4 * tx]);
        float a[4] = {av.x, av.y, av.z, av.w};
        float4 w0 = *reinterpret_cast<const float4*>(&Ws[k][16 * ty + 0]);
        float4 w1 = *reinterpret_cast<const float4*>(&Ws[k][16 * ty + 4]);
        float4 w2 = *reinterpret_cast<const float4*>(&Ws[k][16 * ty + 8]);
        float4 w3 = *reinterpret_cast<const float4*>(&Ws[k][16 * ty + 12]);
        float wv[16] = {w0.x, w0.y, w0.z, w0.w, w1.x, w1.y, w1.z, w1.w,
                        w2.x, w2.y, w2.z, w2.w, w3.x, w3.y, w3.z, w3.w};
#pragma unroll
        for (int i = 0; i < 4; i++)
#pragma unroll
            for (int j = 0; j < 16; j++)
                acc[i][j] = fmaf(a[i], wv[j], acc[i][j]);
    }

    const bool rok = row < n;
    float m[4];
#pragma unroll
    for (int i = 0; i < 4; i++) m[i] = (rok && (4 * tx + i) < n) ? 1.0f : 0.0f;

#pragma unroll
    for (int j = 0; j < 16; j++) {
        const int e = 16 * ty + j;
        __nv_bfloat16* d = dst + ((size_t)(b * OUTD + e)) * (NN * NN)
                               + (size_t)row * NN + 4 * tx;
        __nv_bfloat162 lo = __floats2bfloat162_rn(
            fmaxf(acc[0][j], 0.0f) * m[0], fmaxf(acc[1][j], 0.0f) * m[1]);
        __nv_bfloat162 hi = __floats2bfloat162_rn(
            fmaxf(acc[2][j], 0.0f) * m[2], fmaxf(acc[3][j], 0.0f) * m[3]);
        uint2 pk;
        pk.x = *reinterpret_cast<uint32_t*>(&lo);
        pk.y = *reinterpret_cast<uint32_t*>(&hi);
        *reinterpret_cast<uint2*>(d) = pk;
    }
}

// ---------------------------------------------------------------------------
// Stage 2: 2048 x [128x128x128] bf16 GEMMs via mma.sync (one CTA per (b,e)).
// A = g_s1[be] [i][k] K-major; B = g_s2[be] [j][k] K-major (col-major B).
// 8 warps: warp_m = wid>>2 (64 rows), warp_n = wid&3 (32 cols).
// ---------------------------------------------------------------------------
#define APITCH 136                       // bf16 elems/row (272B: 16B-aligned, ldmatrix conflict-free)
#define S2_B_OFF (NN * APITCH * 2)       // 34816 B
#define CPITCH 132                       // fp32 elems/row for C staging
#define S2_SMEM (2 * NN * APITCH * 2)    // 69632 B (>= C staging 67584)

__device__ __forceinline__ void ldsm_x4(uint32_t& r0, uint32_t& r1,
                                        uint32_t& r2, uint32_t& r3, uint32_t a) {
    asm volatile("ldmatrix.sync.aligned.m8n8.x4.shared.b16 {%0,%1,%2,%3}, [%4];"
                 : "=r"(r0), "=r"(r1), "=r"(r2), "=r"(r3) : "r"(a));
}
__device__ __forceinline__ void mma_bf16(float* c, const uint32_t* a,
                                         uint32_t b0, uint32_t b1) {
    asm volatile(
        "mma.sync.aligned.m16n8k16.row.col.f32.bf16.bf16.f32 "
        "{%0,%1,%2,%3}, {%4,%5,%6,%7}, {%8,%9}, {%0,%1,%2,%3};"
        : "+f"(c[0]), "+f"(c[1]), "+f"(c[2]), "+f"(c[3])
        : "r"(a[0]), "r"(a[1]), "r"(a[2]), "r"(a[3]), "r"(b0), "r"(b1));
}

__global__ void __launch_bounds__(256, 1) stage2_kernel()
{
    extern __shared__ char sm[];
    const uint32_t smb = smem_u32(sm);
    const int tid  = threadIdx.x;
    const int wid  = tid >> 5;
    const int lane = tid & 31;
    const int be   = blockIdx.x;

    // ---- Load A and B tiles (64KB each bf16) into padded smem ----
    const uint4* A4 = reinterpret_cast<const uint4*>(g_s1 + (size_t)be * (NN * NN));
    const uint4* B4 = reinterpret_cast<const uint4*>(g_s2 + (size_t)be * (NN * NN));
#pragma unroll
    for (int it = 0; it < 8; it++) {
        const int l = it * 256 + tid;          // 2048 uint4 per operand
        const int r = l >> 4, c8 = l & 15;
        const uint32_t o = (uint32_t)r * (APITCH * 2) + (uint32_t)c8 * 16;
        *reinterpret_cast<uint4*>(sm + o)            = A4[l];
        *reinterpret_cast<uint4*>(sm + S2_B_OFF + o) = B4[l];
    }
    __syncthreads();

    const int warp_m = wid >> 2;   // 0..1 : rows warp_m*64
    const int warp_n = wid & 3;    // 0..3 : cols warp_n*32

    float acc[4][4][4];            // [mt][nt][4]
#pragma unroll
    for (int mt = 0; mt < 4; mt++)
#pragma unroll
        for (int nt = 0; nt < 4; nt++)
#pragma unroll
            for (int r = 0; r < 4; r++) acc[mt][nt][r] = 0.0f;

    // ldmatrix lane addressing
    const int a_row = (lane & 15);          // within 16-row tile
    const int a_kof = (lane >> 4) * 8;      // 0 or 8
    const int b_nl  = (lane & 7) + ((lane >> 4) << 3);   // n offset within 16
    const int b_kof = ((lane >> 3) & 1) * 8;

#pragma unroll
    for (int kk = 0; kk < 8; kk++) {
        const int k0 = kk * 16;
        uint32_t a[4][4];
#pragma unroll
        for (int mt = 0; mt < 4; mt++) {
            uint32_t ad = smb + (uint32_t)(warp_m * 64 + mt * 16 + a_row) * (APITCH * 2)
                              + (uint32_t)(k0 + a_kof) * 2;
            ldsm_x4(a[mt][0], a[mt][1], a[mt][2], a[mt][3], ad);
        }
        uint32_t bfr[2][4];        // [np][{n0-7 k0, n0-7 k8, n8-15 k0, n8-15 k8}]
#pragma unroll
        for (int np = 0; np < 2; np++) {
            uint32_t bd = smb + S2_B_OFF
                        + (uint32_t)(warp_n * 32 + np * 16 + b_nl) * (APITCH * 2)
                        + (uint32_t)(k0 + b_kof) * 2;
            ldsm_x4(bfr[np][0], bfr[np][1], bfr[np][2], bfr[np][3], bd);
        }
#pragma unroll
        for (int mt = 0; mt < 4; mt++)
#pragma unroll
            for (int nt = 0; nt < 4; nt++)
                mma_bf16(acc[mt][nt], a[mt],
                         bfr[nt >> 1][(nt & 1) * 2 + 0],
                         bfr[nt >> 1][(nt & 1) * 2 + 1]);
    }
    __syncthreads();   // done reading A/B; reuse smem for C

    // ---- Stage C through smem for coalesced stores ----
    float* Cs = reinterpret_cast<float*>(sm);
#pragma unroll
    for (int mt = 0; mt < 4; mt++) {
        const int mrow = warp_m * 64 + mt * 16 + (lane >> 2);
#pragma unroll
        for (int nt = 0; nt < 4; nt++) {
            const int ncol = warp_n * 32 + nt * 8 + (lane & 3) * 2;
            *reinterpret_cast<float2*>(&Cs[mrow * CPITCH + ncol]) =
                make_float2(acc[mt][nt][0], acc[mt][nt][1]);
            *reinterpret_cast<float2*>(&Cs[(mrow + 8) * CPITCH + ncol]) =
                make_float2(acc[mt][nt][2], acc[mt][nt][3]);
        }
    }
    __syncthreads();

    float4* C = reinterpret_cast<float4*>(g_to + (size_t)be * (NN * NN));
#pragma unroll
    for (int it = 0; it < 16; it++) {
        const int l4 = it * 256 + tid;         // 4096 float4
        const int rr = l4 >> 5, c4 = l4 & 31;
        C[l4] = *reinterpret_cast<const float4*>(&Cs[rr * CPITCH + c4 * 4]);
    }
}

// ---------------------------------------------------------------------------
// Final transpose: out[b, x, e] = g_to[b, e, x]
// ---------------------------------------------------------------------------
__global__ void __launch_bounds__(256) transpose_kernel(float* __restrict__ out)
{
    __shared__ float t[32][33];
    const int b  = blockIdx.z;
    const int x0 = blockIdx.x * 32;
    const int e0 = blockIdx.y * 32;
    const int tx = threadIdx.x;
    const int ty = threadIdx.y;

    const float* src = g_to + (size_t)b * OUTD * (NN * NN);
#pragma unroll
    for (int j = 0; j < 32; j += 8)
        t[ty + j][tx] = src[(size_t)(e0 + ty + j) * (NN * NN) + x0 + tx];
    __syncthreads();
#pragma unroll
    for (int j = 0; j < 32; j += 8)
        out[((size_t)b * (NN * NN) + x0 + ty + j) * OUTD + e0 + tx] = t[tx][ty + j];
}

// ---------------------------------------------------------------------------
extern "C" void kernel_launch(void* const* d_in, const int* in_sizes, int n_in,
                              void* d_out, int out_size)
{
    const float* X  = (const float*)d_in[0];
    const float* W1 = (const float*)d_in[1];
    const float* b1 = (const float*)d_in[2];
    const float* W2 = (const float*)d_in[3];
    const float* b2 = (const float*)d_in[4];
    const int*   nn = (const int*)d_in[5];
    float* out = (float*)d_out;

    __nv_bfloat16 *s1, *s2;
    cudaGetSymbolAddress((void**)&s1, g_s1);
    cudaGetSymbolAddress((void**)&s2, g_s2);

    mlp_kernel<<<BB * NN, 128>>>(X, W1, b1, nn, s1, 0);   // X1 -> [b,e,i,k]
    mlp_kernel<<<BB * NN, 128>>>(X, W2, b2, nn, s2, 1);   // X2^T -> [b,e,j,k]

    cudaFuncSetAttribute(stage2_kernel,
                         cudaFuncAttributeMaxDynamicSharedMemorySize, S2_SMEM);
    stage2_kernel<<<BB * OUTD, 256, S2_SMEM>>>();

    dim3 tg(NN * NN / 32, OUTD / 32, BB);
    transpose_kernel<<<tg, dim3(32, 8)>>>(out);
}

// round 8
// speedup vs baseline: 2.4012x; 1.0371x over previous
#include <cuda_runtime.h>
#include <cuda_bf16.h>
#include <cstdint>
#include <cstddef>

// Problem constants
#define BB   32
#define NN   128
#define IND  32
#define OUTD 64

// Scratch (device globals; no allocs allowed)
__device__ __nv_bfloat16 g_s1[(size_t)BB * OUTD * NN * NN];  // X1: [b,e,i,k]
__device__ __nv_bfloat16 g_s2[(size_t)BB * OUTD * NN * NN];  // X2^T: [b,e,j,k]

__device__ __forceinline__ uint32_t smem_u32(const void* p) {
    uint32_t a;
    asm("{ .reg .u64 t; cvta.to.shared.u64 t, %1; cvt.u32.u64 %0, t; }"
        : "=r"(a) : "l"(p));
    return a;
}

// ---------------------------------------------------------------------------
// Fused MLP: both passes in one grid (they are independent).
// pass=0: block=(b,p) computes X1[b,p,t,e]  -> s1[b,e,p,t]   (K-major A)
// pass=1: block=(b,q) computes X2[b,t,q,e]  -> s2[b,e,q,t]   (K-major B^T)
// Grid 8192 (pass = blockIdx.x>>12), 128 threads.
// ---------------------------------------------------------------------------
__global__ void __launch_bounds__(128) mlp_kernel(
    const float* __restrict__ X,
    const float* __restrict__ W1, const float* __restrict__ b1,
    const float* __restrict__ W2, const float* __restrict__ b2,
    const int* __restrict__ nn32,
    __nv_bfloat16* __restrict__ s1, __nv_bfloat16* __restrict__ s2)
{
    __shared__ float Xs[IND][NN];    // [k][t]
    __shared__ float Ws[IND][OUTD];  // [k][e]
    __shared__ float bs[OUTD];

    const int pass = blockIdx.x >> 12;
    const int blk  = blockIdx.x & 4095;
    const int b    = blk >> 7;
    const int row  = blk & 127;
    const int tid  = threadIdx.x;

    const float* __restrict__ W    = pass ? W2 : W1;
    const float* __restrict__ bias = pass ? b2 : b1;
    __nv_bfloat16* __restrict__ dst = pass ? s2 : s1;

    for (int l = tid; l < IND * OUTD; l += 128) Ws[l >> 6][l & 63] = W[l];
    if (tid < OUTD) bs[tid] = bias[tid];

    {   // load this block's 128 X tuple-rows (128B each), transposed into Xs[k][t]
        const int t = tid;
        const size_t xoff = pass ? (((size_t)b * NN + t) * NN + row) * IND
                                 : (((size_t)b * NN + row) * NN + t) * IND;
        const float4* Xp = reinterpret_cast<const float4*>(X + xoff);
#pragma unroll
        for (int c = 0; c < 8; c++) {
            float4 v = Xp[c];
            Xs[4 * c + 0][t] = v.x; Xs[4 * c + 1][t] = v.y;
            Xs[4 * c + 2][t] = v.z; Xs[4 * c + 3][t] = v.w;
        }
    }
    __syncthreads();

    const int n = (nn32[1] == 0) ? nn32[2 * b] : nn32[b];   // int64 vs int32 defense

    const int tx = tid & 31;   // t = 4*tx + i
    const int ty = tid >> 5;   // e = 16*ty + j

    float acc[4][16];
#pragma unroll
    for (int i = 0; i < 4; i++)
#pragma unroll
        for (int j = 0; j < 16; j++) acc[i][j] = bs[16 * ty + j];

#pragma unroll 4
    for (int k = 0; k < IND; k++) {
        float4 av = *reinterpret_cast<const float4*>(&Xs[k][4 * tx]);
        float a[4] = {av.x, av.y, av.z, av.w};
        float4 w0 = *reinterpret_cast<const float4*>(&Ws[k][16 * ty + 0]);
        float4 w1 = *reinterpret_cast<const float4*>(&Ws[k][16 * ty + 4]);
        float4 w2 = *reinterpret_cast<const float4*>(&Ws[k][16 * ty + 8]);
        float4 w3 = *reinterpret_cast<const float4*>(&Ws[k][16 * ty + 12]);
        float wv[16] = {w0.x, w0.y, w0.z, w0.w, w1.x, w1.y, w1.z, w1.w,
                        w2.x, w2.y, w2.z, w2.w, w3.x, w3.y, w3.z, w3.w};
#pragma unroll
        for (int i = 0; i < 4; i++)
#pragma unroll
            for (int j = 0; j < 16; j++)
                acc[i][j] = fmaf(a[i], wv[j], acc[i][j]);
    }

    const bool rok = row < n;
    float m[4];
#pragma unroll
    for (int i = 0; i < 4; i++) m[i] = (rok && (4 * tx + i) < n) ? 1.0f : 0.0f;

#pragma unroll
    for (int j = 0; j < 16; j++) {
        const int e = 16 * ty + j;
        __nv_bfloat16* d = dst + ((size_t)(b * OUTD + e)) * (NN * NN)
                               + (size_t)row * NN + 4 * tx;
        __nv_bfloat162 lo = __floats2bfloat162_rn(
            fmaxf(acc[0][j], 0.0f) * m[0], fmaxf(acc[1][j], 0.0f) * m[1]);
        __nv_bfloat162 hi = __floats2bfloat162_rn(
            fmaxf(acc[2][j], 0.0f) * m[2], fmaxf(acc[3][j], 0.0f) * m[3]);
        uint2 pk;
        pk.x = *reinterpret_cast<uint32_t*>(&lo);
        pk.y = *reinterpret_cast<uint32_t*>(&hi);
        *reinterpret_cast<uint2*>(d) = pk;
    }
}

// ---------------------------------------------------------------------------
// Stage 2: 2048 x [128x128x128] bf16 mma.sync GEMMs, one CTA per (b,e),
// launched as clusters of 8 = one e-octet of the same b. After the GEMM each
// CTA stages C in smem; a DSMEM exchange then assembles out[b,i,j,e0:e0+8]
// directly (32B-sector-perfect stores). No fp32 intermediate, no transpose.
// ---------------------------------------------------------------------------
#define APITCH 136                       // bf16/row: 272B, 16B-aligned, LDSM conflict-free
#define S2_B_OFF (NN * APITCH * 2)       // 34816 B
#define CPITCH 132                       // fp32/row for C staging
#define S2_SMEM (2 * NN * APITCH * 2)    // 69632 B (>= C staging 67584)
#define CLU 8

__device__ __forceinline__ void ldsm_x4(uint32_t& r0, uint32_t& r1,
                                        uint32_t& r2, uint32_t& r3, uint32_t a) {
    asm volatile("ldmatrix.sync.aligned.m8n8.x4.shared.b16 {%0,%1,%2,%3}, [%4];"
                 : "=r"(r0), "=r"(r1), "=r"(r2), "=r"(r3) : "r"(a));
}
__device__ __forceinline__ void mma_bf16(float* c, const uint32_t* a,
                                         uint32_t b0, uint32_t b1) {
    asm volatile(
        "mma.sync.aligned.m16n8k16.row.col.f32.bf16.bf16.f32 "
        "{%0,%1,%2,%3}, {%4,%5,%6,%7}, {%8,%9}, {%0,%1,%2,%3};"
        : "+f"(c[0]), "+f"(c[1]), "+f"(c[2]), "+f"(c[3])
        : "r"(a[0]), "r"(a[1]), "r"(a[2]), "r"(a[3]), "r"(b0), "r"(b1));
}
__device__ __forceinline__ float4 dsmem_ld4(uint32_t local_addr, uint32_t rank) {
    uint32_t r; float4 v;
    asm volatile("mapa.shared::cluster.u32 %0, %1, %2;"
                 : "=r"(r) : "r"(local_addr), "r"(rank));
    asm volatile("ld.shared::cluster.v4.f32 {%0,%1,%2,%3}, [%4];"
                 : "=f"(v.x), "=f"(v.y), "=f"(v.z), "=f"(v.w) : "r"(r));
    return v;
}

__global__ void __launch_bounds__(256, 1) stage2_kernel(float* __restrict__ out)
{
    extern __shared__ char sm[];
    const uint32_t smb = smem_u32(sm);
    const int tid  = threadIdx.x;
    const int wid  = tid >> 5;
    const int lane = tid & 31;
    const int be   = blockIdx.x;
    const int b    = be >> 6;
    uint32_t rank;
    asm("mov.u32 %0, %%cluster_ctarank;" : "=r"(rank));

    // ---- Load A and B tiles (64KB each bf16) into padded smem ----
    const uint4* A4 = reinterpret_cast<const uint4*>(g_s1 + (size_t)be * (NN * NN));
    const uint4* B4 = reinterpret_cast<const uint4*>(g_s2 + (size_t)be * (NN * NN));
#pragma unroll
    for (int it = 0; it < 8; it++) {
        const int l = it * 256 + tid;          // 2048 uint4 per operand
        const int r = l >> 4, c8 = l & 15;
        const uint32_t o = (uint32_t)r * (APITCH * 2) + (uint32_t)c8 * 16;
        *reinterpret_cast<uint4*>(sm + o)            = A4[l];
        *reinterpret_cast<uint4*>(sm + S2_B_OFF + o) = B4[l];
    }
    __syncthreads();

    const int warp_m = wid >> 2;   // rows warp_m*64
    const int warp_n = wid & 3;    // cols warp_n*32

    float acc[4][4][4];
#pragma unroll
    for (int mt = 0; mt < 4; mt++)
#pragma unroll
        for (int nt = 0; nt < 4; nt++)
#pragma unroll
            for (int r = 0; r < 4; r++) acc[mt][nt][r] = 0.0f;

    const int a_row = (lane & 15);
    const int a_kof = (lane >> 4) * 8;
    const int b_nl  = (lane & 7) + ((lane >> 4) << 3);
    const int b_kof = ((lane >> 3) & 1) * 8;

#pragma unroll
    for (int kk = 0; kk < 8; kk++) {
        const int k0 = kk * 16;
        uint32_t a[4][4];
#pragma unroll
        for (int mt = 0; mt < 4; mt++) {
            uint32_t ad = smb + (uint32_t)(warp_m * 64 + mt * 16 + a_row) * (APITCH * 2)
                              + (uint32_t)(k0 + a_kof) * 2;
            ldsm_x4(a[mt][0], a[mt][1], a[mt][2], a[mt][3], ad);
        }
        uint32_t bfr[2][4];
#pragma unroll
        for (int np = 0; np < 2; np++) {
            uint32_t bd = smb + S2_B_OFF
                        + (uint32_t)(warp_n * 32 + np * 16 + b_nl) * (APITCH * 2)
                        + (uint32_t)(k0 + b_kof) * 2;
            ldsm_x4(bfr[np][0], bfr[np][1], bfr[np][2], bfr[np][3], bd);
        }
#pragma unroll
        for (int mt = 0; mt < 4; mt++)
#pragma unroll
            for (int nt = 0; nt < 4; nt++)
                mma_bf16(acc[mt][nt], a[mt],
                         bfr[nt >> 1][(nt & 1) * 2 + 0],
                         bfr[nt >> 1][(nt & 1) * 2 + 1]);
    }
    __syncthreads();   // done reading A/B; reuse smem for C

    // ---- Stage C into own smem [128][CPITCH] ----
    float* Cs = reinterpret_cast<float*>(sm);
#pragma unroll
    for (int mt = 0; mt < 4; mt++) {
        const int mrow = warp_m * 64 + mt * 16 + (lane >> 2);
#pragma unroll
        for (int nt = 0; nt < 4; nt++) {
            const int ncol = warp_n * 32 + nt * 8 + (lane & 3) * 2;
            *reinterpret_cast<float2*>(&Cs[mrow * CPITCH + ncol]) =
                make_float2(acc[mt][nt][0], acc[mt][nt][1]);
            *reinterpret_cast<float2*>(&Cs[(mrow + 8) * CPITCH + ncol]) =
                make_float2(acc[mt][nt][2], acc[mt][nt][3]);
        }
    }

    // ---- Cluster barrier: all 8 siblings' C tiles ready ----
    asm volatile("barrier.cluster.arrive.aligned;" ::: "memory");
    asm volatile("barrier.cluster.wait.aligned;" ::: "memory");

    // ---- DSMEM exchange: rank owns i in [16*rank, 16*rank+16).
    // For each (i, j-quad), gather float4 over j from all 8 siblings, then
    // emit e-contiguous stores: out[b,i,j, e_base..e_base+7] (2x STG.128).
    const int e_base = (be & ~(CLU - 1)) & 63;      // e octet base
#pragma unroll
    for (int it = 0; it < 2; it++) {
        const int idx  = it * 256 + tid;            // 0..511
        const int iloc = idx >> 5;                  // 0..15
        const int j0   = (idx & 31) * 4;            // 0,4,..,124
        const int i    = (int)rank * 16 + iloc;
        const uint32_t laddr = smb + (uint32_t)(i * CPITCH + j0) * 4;

        float4 c[CLU];
#pragma unroll
        for (int s = 0; s < CLU; s++) c[s] = dsmem_ld4(laddr, (uint32_t)s);

        float* op = out + (((size_t)b * NN + i) * NN + j0) * OUTD + e_base;
#pragma unroll
        for (int jj = 0; jj < 4; jj++) {
            float v[8] = {
                (&c[0].x)[jj], (&c[1].x)[jj], (&c[2].x)[jj], (&c[3].x)[jj],
                (&c[4].x)[jj], (&c[5].x)[jj], (&c[6].x)[jj], (&c[7].x)[jj]};
            float* o = op + (size_t)jj * OUTD;
            *reinterpret_cast<float4*>(o)     = make_float4(v[0], v[1], v[2], v[3]);
            *reinterpret_cast<float4*>(o + 4) = make_float4(v[4], v[5], v[6], v[7]);
        }
    }

    // ---- Protect smem until all siblings finished reading ----
    asm volatile("barrier.cluster.arrive.aligned;" ::: "memory");
    asm volatile("barrier.cluster.wait.aligned;" ::: "memory");
}

// ---------------------------------------------------------------------------
extern "C" void kernel_launch(void* const* d_in, const int* in_sizes, int n_in,
                              void* d_out, int out_size)
{
    const float* X  = (const float*)d_in[0];
    const float* W1 = (const float*)d_in[1];
    const float* b1 = (const float*)d_in[2];
    const float* W2 = (const float*)d_in[3];
    const float* b2 = (const float*)d_in[4];
    const int*   nn = (const int*)d_in[5];
    float* out = (float*)d_out;

    __nv_bfloat16 *s1, *s2;
    cudaGetSymbolAddress((void**)&s1, g_s1);
    cudaGetSymbolAddress((void**)&s2, g_s2);

    // Fused MLP (both passes, one grid)
    mlp_kernel<<<2 * BB * NN, 128>>>(X, W1, b1, W2, b2, nn, s1, s2);

    // Stage 2 as clusters of 8 (one e-octet per cluster)
    static bool configured = false;
    if (!configured) {
        cudaFuncSetAttribute(stage2_kernel,
                             cudaFuncAttributeMaxDynamicSharedMemorySize, S2_SMEM);
        configured = true;
    }
    cudaLaunchConfig_t cfg = {};
    cfg.gridDim  = dim3(BB * OUTD, 1, 1);
    cfg.blockDim = dim3(256, 1, 1);
    cfg.dynamicSmemBytes = S2_SMEM;
    cudaLaunchAttribute attrs[1];
    attrs[0].id = cudaLaunchAttributeClusterDimension;
    attrs[0].val.clusterDim = {CLU, 1, 1};
    cfg.attrs = attrs;
    cfg.numAttrs = 1;
    cudaLaunchKernelEx(&cfg, stage2_kernel, out);
}